// round 1
// baseline (speedup 1.0000x reference)
#include <cuda_runtime.h>
#include <cuda_bf16.h>

// Problem constants (fixed by setup_inputs):
//   x: [B=2, C=3, D=128, H=160, W=160] float32, num_steps = 6
#define BB    2
#define DD    128
#define HH    160
#define WW    160
#define PLANE (DD * HH * WW)          // 3,276,800 elems per channel plane
#define VOL   (BB * 3 * PLANE)        // 19,660,800 elems total
#define NSTEPS 6

// Ping-pong scratch (allocation-free rule: __device__ globals).
__device__ float g_bufA[VOL];
__device__ float g_bufB[VOL];

// One squaring step, scale applied on read:
//   out(p) = s*src(p) + s*src(q),  q = clamp(round(p + s*src_flow(p)))
// Threads: one per 4 consecutive W voxels (float4 streams, scalar gathers).
__global__ __launch_bounds__(256) void sq_step(const float* __restrict__ src,
                                               float* __restrict__ dst,
                                               float s) {
    const int W4 = WW / 4;
    int idx = blockIdx.x * blockDim.x + threadIdx.x;
    const int total = BB * DD * HH * W4;
    if (idx >= total) return;

    int w4 = idx % W4;
    int t  = idx / W4;
    int h  = t % HH;  t /= HH;
    int d  = t % DD;
    int b  = t / DD;

    const int p = (d * HH + h) * WW + w4 * 4;
    const float* __restrict__ sb = src + (size_t)b * 3 * PLANE;
    float* __restrict__ db       = dst + (size_t)b * 3 * PLANE;

    float4 f0 = *reinterpret_cast<const float4*>(sb + p);
    float4 f1 = *reinterpret_cast<const float4*>(sb + p + PLANE);
    float4 f2 = *reinterpret_cast<const float4*>(sb + p + 2 * PLANE);

    // v = s * src  (s is a power of two -> exact, matches reference's x/2^n)
    f0.x *= s; f0.y *= s; f0.z *= s; f0.w *= s;
    f1.x *= s; f1.y *= s; f1.z *= s; f1.w *= s;
    f2.x *= s; f2.y *= s; f2.z *= s; f2.w *= s;

    float fd[4] = {f0.x, f0.y, f0.z, f0.w};
    float fh[4] = {f1.x, f1.y, f1.z, f1.w};
    float fw[4] = {f2.x, f2.y, f2.z, f2.w};
    float o0[4], o1[4], o2[4];

#pragma unroll
    for (int j = 0; j < 4; ++j) {
        // __float2int_rn = round-to-nearest-even, matches jnp.round exactly.
        int id = __float2int_rn((float)d + fd[j]);
        int ih = __float2int_rn((float)h + fh[j]);
        int iw = __float2int_rn((float)(w4 * 4 + j) + fw[j]);
        id = min(max(id, 0), DD - 1);
        ih = min(max(ih, 0), HH - 1);
        iw = min(max(iw, 0), WW - 1);
        const int q = (id * HH + ih) * WW + iw;
        o0[j] = fd[j] + s * sb[q];
        o1[j] = fh[j] + s * sb[q + PLANE];
        o2[j] = fw[j] + s * sb[q + 2 * PLANE];
    }

    *reinterpret_cast<float4*>(db + p)              = make_float4(o0[0], o0[1], o0[2], o0[3]);
    *reinterpret_cast<float4*>(db + p + PLANE)      = make_float4(o1[0], o1[1], o1[2], o1[3]);
    *reinterpret_cast<float4*>(db + p + 2 * PLANE)  = make_float4(o2[0], o2[1], o2[2], o2[3]);
}

extern "C" void kernel_launch(void* const* d_in, const int* in_sizes, int n_in,
                              void* d_out, int out_size) {
    const float* x   = (const float*)d_in[0];
    float*       out = (float*)d_out;

    float *A = nullptr, *B = nullptr;
    cudaGetSymbolAddress((void**)&A, g_bufA);
    cudaGetSymbolAddress((void**)&B, g_bufB);

    const int W4     = WW / 4;
    const int total  = BB * DD * HH * W4;     // 1,638,400 threads
    const int tpb    = 256;
    const int blocks = (total + tpb - 1) / tpb;

    const float s0 = 1.0f / 64.0f;            // 1 / 2^num_steps (num_steps = 6)

    // 6 steps, scale fused into step 1, final step writes d_out directly.
    sq_step<<<blocks, tpb>>>(x, A, s0);       // v1 = v0 + warp(v0), v0 = x/64
    sq_step<<<blocks, tpb>>>(A, B, 1.0f);
    sq_step<<<blocks, tpb>>>(B, A, 1.0f);
    sq_step<<<blocks, tpb>>>(A, B, 1.0f);
    sq_step<<<blocks, tpb>>>(B, A, 1.0f);
    sq_step<<<blocks, tpb>>>(A, out, 1.0f);
}